// round 1
// baseline (speedup 1.0000x reference)
#include <cuda_runtime.h>
#include <cuda_bf16.h>

#define N_NODES  1000000
#define N_EDGES  16000000
#define N_GRAPHS 10000
#define HIDDEN   64

// Scratch: node features x and accumulator (x + sum of neighbor x), as float4
// pairs (32B per node, 16B aligned for LDG.128 / RED.128).
__device__ float4 g_x[N_NODES * 2];
__device__ float4 g_acc[N_NODES * 2];

// ---------------------------------------------------------------------------
// Kernel 0: out[g] = fcb[0]  (d_out is poisoned before timing)
// ---------------------------------------------------------------------------
__global__ void k_init_out(float* __restrict__ out, const float* __restrict__ fcb) {
    int i = blockIdx.x * blockDim.x + threadIdx.x;
    if (i < N_GRAPHS) out[i] = fcb[0];
}

// ---------------------------------------------------------------------------
// Kernel 1: build x = [pos | emb[z]] and initialize acc = x
// (so that after edge scatter, acc = x + sum_{j->i} x_j directly)
// ---------------------------------------------------------------------------
__global__ void k_build_x(const float* __restrict__ pos,
                          const int*   __restrict__ z,
                          const float* __restrict__ emb) {
    int i = blockIdx.x * blockDim.x + threadIdx.x;
    if (i >= N_NODES) return;
    int zi = z[i];
    const float* e = emb + zi * 5;
    float4 lo = make_float4(pos[3 * i + 0], pos[3 * i + 1], pos[3 * i + 2], e[0]);
    float4 hi = make_float4(e[1], e[2], e[3], e[4]);
    g_x[2 * i + 0]   = lo;
    g_x[2 * i + 1]   = hi;
    g_acc[2 * i + 0] = lo;
    g_acc[2 * i + 1] = hi;
}

// ---------------------------------------------------------------------------
// Kernel 2: edge scatter-add.  acc[dst] += x[src]  (8 floats / edge)
// x (32MB) and acc (32MB) are L2-resident; edge_index streams from DRAM.
// red.global.add.v4.f32 (sm_90+) -> 2 vector reductions per edge.
// ---------------------------------------------------------------------------
__global__ void k_edges(const int* __restrict__ ei) {
    int e = blockIdx.x * blockDim.x + threadIdx.x;
    if (e >= N_EDGES) return;
    int s = ei[e];
    int d = ei[N_EDGES + e];
    float4 lo = __ldg(&g_x[2 * s + 0]);
    float4 hi = __ldg(&g_x[2 * s + 1]);
    float4* p = &g_acc[2 * d];
    asm volatile("red.global.add.v4.f32 [%0], {%1,%2,%3,%4};"
                 :: "l"(p), "f"(lo.x), "f"(lo.y), "f"(lo.z), "f"(lo.w) : "memory");
    asm volatile("red.global.add.v4.f32 [%0], {%1,%2,%3,%4};"
                 :: "l"(p + 1), "f"(hi.x), "f"(hi.y), "f"(hi.z), "f"(hi.w) : "memory");
}

// ---------------------------------------------------------------------------
// Kernel 3: per-node MLP + pooled dot with fcW, segment-add into out[batch[i]].
//   h1 = relu(acc @ W1 + b1)          [8 -> 64]
//   h2 = relu(h1 @ W2 + b2)           [64 -> 64]
//   s  = h2 . fcW                     scalar
//   out[batch[i]] += s   (warp-segmented reduction; batch is sorted)
// ---------------------------------------------------------------------------
__global__ void __launch_bounds__(128)
k_mlp(const float* __restrict__ W1, const float* __restrict__ b1,
      const float* __restrict__ W2, const float* __restrict__ b2,
      const float* __restrict__ fcW,
      const int*   __restrict__ batch,
      float* __restrict__ out) {
    __shared__ float sW1[8 * 64];
    __shared__ float sW2[64 * 64];
    __shared__ float sb1[64], sb2[64], sfc[64];

    int t = threadIdx.x;
    for (int k = t; k < 8 * 64; k += 128)  sW1[k] = W1[k];
    for (int k = t; k < 64 * 64; k += 128) sW2[k] = W2[k];
    if (t < 64) { sb1[t] = b1[t]; sb2[t] = b2[t]; sfc[t] = fcW[t]; }
    __syncthreads();

    int i = blockIdx.x * blockDim.x + t;
    float s = 0.0f;
    int   g = -1;

    if (i < N_NODES) {
        g = batch[i];
        float4 lo = g_acc[2 * i + 0];
        float4 hi = g_acc[2 * i + 1];
        float in[8] = { lo.x, lo.y, lo.z, lo.w, hi.x, hi.y, hi.z, hi.w };

        // Layer 1: h1[64] = relu(in @ W1 + b1). h1 lives in local memory so
        // the layer-2 k-loop can stay rolled (dynamic index).
        float h1[64];
        #pragma unroll
        for (int c = 0; c < 4; c++) {
            float a0[16];
            #pragma unroll
            for (int j = 0; j < 16; j++) a0[j] = sb1[c * 16 + j];
            #pragma unroll
            for (int k = 0; k < 8; k++) {
                const float4* w4 = (const float4*)(sW1 + k * 64 + c * 16);
                float ik = in[k];
                #pragma unroll
                for (int j4 = 0; j4 < 4; j4++) {
                    float4 w = w4[j4];
                    a0[j4 * 4 + 0] += ik * w.x;
                    a0[j4 * 4 + 1] += ik * w.y;
                    a0[j4 * 4 + 2] += ik * w.z;
                    a0[j4 * 4 + 3] += ik * w.w;
                }
            }
            #pragma unroll
            for (int j = 0; j < 16; j++) h1[c * 16 + j] = fmaxf(a0[j], 0.0f);
        }

        // Layer 2: acc[64] in registers, k-loop dynamic (~90-instr body, I$-friendly),
        // 16 independent FMA chains per k step for ILP.
        float acc[64];
        #pragma unroll
        for (int j = 0; j < 64; j++) acc[j] = sb2[j];

        for (int k = 0; k < 64; k++) {
            float hk = h1[k];                       // LDL (local)
            const float4* w4 = (const float4*)(sW2 + (k << 6));
            #pragma unroll
            for (int j4 = 0; j4 < 16; j4++) {
                float4 w = w4[j4];                  // LDS.128, warp-broadcast
                acc[j4 * 4 + 0] += hk * w.x;
                acc[j4 * 4 + 1] += hk * w.y;
                acc[j4 * 4 + 2] += hk * w.z;
                acc[j4 * 4 + 3] += hk * w.w;
            }
        }

        #pragma unroll
        for (int j = 0; j < 64; j++)
            s += fmaxf(acc[j], 0.0f) * sfc[j];
    }

    // Warp-segmented suffix reduction (batch sorted -> segments contiguous).
    const unsigned full = 0xffffffffu;
    int lane = t & 31;
    #pragma unroll
    for (int d = 1; d < 32; d <<= 1) {
        float v  = __shfl_down_sync(full, s, d);
        int   go = __shfl_down_sync(full, g, d);
        if (lane + d < 32 && go == g) s += v;
    }
    int gup = __shfl_up_sync(full, g, 1);
    if (g >= 0 && (lane == 0 || gup != g))
        atomicAdd(&out[g], s);
}

// ---------------------------------------------------------------------------
// launch
// ---------------------------------------------------------------------------
extern "C" void kernel_launch(void* const* d_in, const int* in_sizes, int n_in,
                              void* d_out, int out_size) {
    const float* pos   = (const float*)d_in[0];
    const int*   z     = (const int*)  d_in[1];
    const int*   ei    = (const int*)  d_in[2];
    const int*   batch = (const int*)  d_in[3];
    const float* emb   = (const float*)d_in[4];
    const float* W1    = (const float*)d_in[5];
    const float* b1    = (const float*)d_in[6];
    const float* W2    = (const float*)d_in[7];
    const float* b2    = (const float*)d_in[8];
    const float* fcW   = (const float*)d_in[9];
    const float* fcb   = (const float*)d_in[10];
    float* out = (float*)d_out;

    k_init_out<<<(N_GRAPHS + 255) / 256, 256>>>(out, fcb);
    k_build_x<<<(N_NODES + 255) / 256, 256>>>(pos, z, emb);
    k_edges<<<(N_EDGES + 255) / 256, 256>>>(ei);
    k_mlp<<<(N_NODES + 127) / 128, 128>>>(W1, b1, W2, b2, fcW, batch, out);
}

// round 4
// speedup vs baseline: 1.2359x; 1.2359x over previous
#include <cuda_runtime.h>
#include <cuda_bf16.h>

#define N_NODES  1000000
#define N_EDGES  16000000
#define N_GRAPHS 10000

// Scratch: node features x and accumulator (x + sum of neighbor x), as float4
// pairs (32B per node, 16B aligned for LDG.128 / RED.128).
__device__ float4 g_x[N_NODES * 2];
__device__ float4 g_acc[N_NODES * 2];

// ---------------------------------------------------------------------------
// Kernel 0: out[g] = fcb[0]  (d_out is poisoned before timing)
// ---------------------------------------------------------------------------
__global__ void k_init_out(float* __restrict__ out, const float* __restrict__ fcb) {
    int i = blockIdx.x * blockDim.x + threadIdx.x;
    if (i < N_GRAPHS) out[i] = fcb[0];
}

// ---------------------------------------------------------------------------
// Kernel 1: build x = [pos | emb[z]] and initialize acc = x
// ---------------------------------------------------------------------------
__global__ void k_build_x(const float* __restrict__ pos,
                          const int*   __restrict__ z,
                          const float* __restrict__ emb) {
    int i = blockIdx.x * blockDim.x + threadIdx.x;
    if (i >= N_NODES) return;
    int zi = z[i];
    const float* e = emb + zi * 5;
    float4 lo = make_float4(pos[3 * i + 0], pos[3 * i + 1], pos[3 * i + 2], e[0]);
    float4 hi = make_float4(e[1], e[2], e[3], e[4]);
    g_x[2 * i + 0]   = lo;
    g_x[2 * i + 1]   = hi;
    g_acc[2 * i + 0] = lo;
    g_acc[2 * i + 1] = hi;
}

// ---------------------------------------------------------------------------
// Kernel 2: edge scatter-add.  acc[dst] += x[src]  (8 floats / edge)
// edge_index streamed with .cs hint (read once, don't pollute L2);
// x/acc stay L2-resident. red.global.add.v4.f32 -> 2 vector REDs per edge.
// ---------------------------------------------------------------------------
__global__ void k_edges(const int* __restrict__ ei) {
    int e = blockIdx.x * blockDim.x + threadIdx.x;
    if (e >= N_EDGES) return;
    int s = __ldcs(&ei[e]);
    int d = __ldcs(&ei[N_EDGES + e]);
    float4 lo = __ldg(&g_x[2 * s + 0]);
    float4 hi = __ldg(&g_x[2 * s + 1]);
    float4* p = &g_acc[2 * d];
    asm volatile("red.global.add.v4.f32 [%0], {%1,%2,%3,%4};"
                 :: "l"(p), "f"(lo.x), "f"(lo.y), "f"(lo.z), "f"(lo.w) : "memory");
    asm volatile("red.global.add.v4.f32 [%0], {%1,%2,%3,%4};"
                 :: "l"(p + 1), "f"(hi.x), "f"(hi.y), "f"(hi.z), "f"(hi.w) : "memory");
}

// ---------------------------------------------------------------------------
// Kernel 3 (v2): per-THREAD handles TWO nodes; layer-2 uses packed f32x2 FMA
// and ld.shared.v2.u64 weight loads (weights shared by both nodes).
// Output columns split into 2 halves of 32 to bound register pressure.
//   h1 = relu(acc @ W1 + b1)          [8 -> 64]
//   h2 = relu(h1 @ W2 + b2)           [64 -> 64]
//   s  = h2 . fcW                     scalar
//   out[batch[i]] += s   (warp-segmented reduction; batch is sorted)
// ---------------------------------------------------------------------------
__global__ void __launch_bounds__(128)
k_mlp(const float* __restrict__ W1, const float* __restrict__ b1,
      const float* __restrict__ W2, const float* __restrict__ b2,
      const float* __restrict__ fcW,
      const int*   __restrict__ batch,
      float* __restrict__ out) {
    __shared__ float sW1[8 * 64];
    __shared__ float sW2[64 * 64];
    __shared__ float sb1[64], sb2[64], sfc[64];

    int t = threadIdx.x;
    for (int k = t; k < 8 * 64; k += 128)  sW1[k] = W1[k];
    for (int k = t; k < 64 * 64; k += 128) sW2[k] = W2[k];
    if (t < 64) { sb1[t] = b1[t]; sb2[t] = b2[t]; sfc[t] = fcW[t]; }
    __syncthreads();

    int base = blockIdx.x * 256;
    int idx[2] = { base + t, base + 128 + t };
    int   g[2] = { -1, -1 };
    float s[2] = { 0.0f, 0.0f };
    float h1[2][64];          // dynamic k-index in layer 2 -> local memory

    // ---- Layer 1 for both nodes ----
    #pragma unroll
    for (int nn = 0; nn < 2; nn++) {
        int i = idx[nn];
        float in8[8] = {0,0,0,0,0,0,0,0};
        if (i < N_NODES) {
            g[nn] = batch[i];
            float4 lo = g_acc[2 * i + 0];
            float4 hi = g_acc[2 * i + 1];
            in8[0]=lo.x; in8[1]=lo.y; in8[2]=lo.z; in8[3]=lo.w;
            in8[4]=hi.x; in8[5]=hi.y; in8[6]=hi.z; in8[7]=hi.w;
        }
        #pragma unroll
        for (int c = 0; c < 4; c++) {
            float a0[16];
            #pragma unroll
            for (int j = 0; j < 16; j++) a0[j] = sb1[c * 16 + j];
            #pragma unroll
            for (int k = 0; k < 8; k++) {
                const float4* w4 = (const float4*)(sW1 + k * 64 + c * 16);
                float ik = in8[k];
                #pragma unroll
                for (int j4 = 0; j4 < 4; j4++) {
                    float4 w = w4[j4];
                    a0[j4 * 4 + 0] += ik * w.x;
                    a0[j4 * 4 + 1] += ik * w.y;
                    a0[j4 * 4 + 2] += ik * w.z;
                    a0[j4 * 4 + 3] += ik * w.w;
                }
            }
            #pragma unroll
            for (int j = 0; j < 16; j++) h1[nn][c * 16 + j] = fmaxf(a0[j], 0.0f);
        }
    }

    // ---- Layer 2: halves of 32 output columns, packed f32x2 FMA ----
    unsigned sW2s = (unsigned)__cvta_generic_to_shared(sW2);
    #pragma unroll
    for (int h = 0; h < 2; h++) {
        unsigned long long A0[16], A1[16];
        #pragma unroll
        for (int p = 0; p < 16; p++) {
            float blo = sb2[h * 32 + 2 * p], bhi = sb2[h * 32 + 2 * p + 1];
            asm("mov.b64 %0, {%1,%2};" : "=l"(A0[p]) : "f"(blo), "f"(bhi));
            A1[p] = A0[p];
        }
        for (int k = 0; k < 64; k++) {
            float hk0 = h1[0][k];
            float hk1 = h1[1][k];
            unsigned long long H0, H1;
            asm("mov.b64 %0, {%1,%1};" : "=l"(H0) : "f"(hk0));
            asm("mov.b64 %0, {%1,%1};" : "=l"(H1) : "f"(hk1));
            unsigned waddr = sW2s + (unsigned)((k * 64 + h * 32) * 4);
            #pragma unroll
            for (int j = 0; j < 8; j++) {
                unsigned long long wlo, whi;
                asm volatile("ld.shared.v2.u64 {%0,%1}, [%2];"
                             : "=l"(wlo), "=l"(whi) : "r"(waddr + j * 16));
                asm("fma.rn.f32x2 %0, %1, %2, %0;" : "+l"(A0[2*j  ]) : "l"(wlo), "l"(H0));
                asm("fma.rn.f32x2 %0, %1, %2, %0;" : "+l"(A0[2*j+1]) : "l"(whi), "l"(H0));
                asm("fma.rn.f32x2 %0, %1, %2, %0;" : "+l"(A1[2*j  ]) : "l"(wlo), "l"(H1));
                asm("fma.rn.f32x2 %0, %1, %2, %0;" : "+l"(A1[2*j+1]) : "l"(whi), "l"(H1));
            }
        }
        // relu + dot with fcW for this half
        #pragma unroll
        for (int p = 0; p < 16; p++) {
            float f0 = sfc[h * 32 + 2 * p], f1 = sfc[h * 32 + 2 * p + 1];
            float lo, hi;
            asm("mov.b64 {%0,%1}, %2;" : "=f"(lo), "=f"(hi) : "l"(A0[p]));
            s[0] += fmaxf(lo, 0.0f) * f0 + fmaxf(hi, 0.0f) * f1;
            asm("mov.b64 {%0,%1}, %2;" : "=f"(lo), "=f"(hi) : "l"(A1[p]));
            s[1] += fmaxf(lo, 0.0f) * f0 + fmaxf(hi, 0.0f) * f1;
        }
    }

    // ---- Warp-segmented suffix reductions (batch sorted) ----
    const unsigned full = 0xffffffffu;
    int lane = t & 31;
    #pragma unroll
    for (int nn = 0; nn < 2; nn++) {
        float sv = s[nn];
        int   gv = g[nn];
        #pragma unroll
        for (int d = 1; d < 32; d <<= 1) {
            float v  = __shfl_down_sync(full, sv, d);
            int   go = __shfl_down_sync(full, gv, d);
            if (lane + d < 32 && go == gv) sv += v;
        }
        int gup = __shfl_up_sync(full, gv, 1);
        if (gv >= 0 && (lane == 0 || gup != gv))
            atomicAdd(&out[gv], sv);
    }
}

// ---------------------------------------------------------------------------
// launch
// ---------------------------------------------------------------------------
extern "C" void kernel_launch(void* const* d_in, const int* in_sizes, int n_in,
                              void* d_out, int out_size) {
    const float* pos   = (const float*)d_in[0];
    const int*   z     = (const int*)  d_in[1];
    const int*   ei    = (const int*)  d_in[2];
    const int*   batch = (const int*)  d_in[3];
    const float* emb   = (const float*)d_in[4];
    const float* W1    = (const float*)d_in[5];
    const float* b1    = (const float*)d_in[6];
    const float* W2    = (const float*)d_in[7];
    const float* b2    = (const float*)d_in[8];
    const float* fcW   = (const float*)d_in[9];
    const float* fcb   = (const float*)d_in[10];
    float* out = (float*)d_out;

    k_init_out<<<(N_GRAPHS + 255) / 256, 256>>>(out, fcb);
    k_build_x<<<(N_NODES + 255) / 256, 256>>>(pos, z, emb);
    k_edges<<<(N_EDGES + 255) / 256, 256>>>(ei);
    k_mlp<<<(N_NODES + 255) / 256, 128>>>(W1, b1, W2, b2, fcW, batch, out);
}